// round 14
// baseline (speedup 1.0000x reference)
#include <cuda_runtime.h>
#include <cuda_fp16.h>
#include <stdint.h>

// ---------------- problem constants ----------------
#define SEQ      2048
#define M_TOK    65536          // 32 * 2048 tokens
#define HIDDEN   512
#define VOCAB    1024
#define KDIM     512
#define BUCKETS  4096

// ---------------- GEMM tiling ----------------
#define BM 128                  // block M tile
#define BN 128                  // block N tile
#define BK 32                   // K chunk (halves)
#define NKIT (KDIM / BK)        // 16
#define NSTAGE 3
#define SPAD 40                 // padded smem row stride in halves (conflict-free ldmatrix)

// ---------------- scratch (no allocs allowed) ----------------
__device__ __half g_feat[(size_t)M_TOK * HIDDEN];   // 64 MB
__device__ __half g_hA  [(size_t)M_TOK * HIDDEN];   // 64 MB
__device__ __half g_hB  [(size_t)M_TOK * HIDDEN];   // 64 MB
__device__ __half g_w   [4 * HIDDEN * HIDDEN + VOCAB * HIDDEN]; // fp16 weights

// ---------------- hash constants (bit-exact vs reference) ----------------
__constant__ long long c_primes[24] = {
    2654435761LL, 2246822519LL, 3266489917LL, 2028178513LL, 1220703125LL,
    1610612741LL, 805306457LL,  402653189LL,  3674653429LL, 2860486313LL,
    1073676287LL, 2971215073LL, 1500450271LL, 3267000013LL, 2654435789LL,
    4049292737LL, 2246822531LL, 3266489927LL, 2028178519LL, 1220703133LL,
    1610612743LL, 805306459LL,  402653191LL,  3674653433LL};

__constant__ int c_plen[32] = {1,1,1,1,1,1,1,1,
                               2,2,2,2,2,2,2,2,2,2,2,2,
                               3,3,3,3,3,3,3,3,
                               2,2,2,2};
__constant__ int c_poff[32][3] = {
    {1,0,0},{2,0,0},{3,0,0},{4,0,0},{5,0,0},{6,0,0},{7,0,0},{8,0,0},
    {1,2,0},{2,3,0},{3,4,0},{1,3,0},{2,4,0},{1,4,0},{1,5,0},{2,5,0},
    {3,5,0},{1,6,0},{2,6,0},{1,7,0},
    {1,2,3},{1,2,4},{1,3,5},{2,3,4},{1,2,5},{1,3,4},{2,4,6},{1,4,7},
    {1,8,0},{1,9,0},{1,10,0},{1,11,0}};

// ---------------- fused feature + weight-convert kernel ----------------
#define FEAT_BLOCKS 8192
#define WCVT_F4     393216      // (4*512*512 + 1024*512) / 4 float4 elements
#define WCVT_BLOCKS 1536        // WCVT_F4 / 256

__global__ void prep_kernel(const int* __restrict__ chars,
                            const float* __restrict__ byte_embed,
                            const float* __restrict__ hash_tables,
                            const float* __restrict__ w_in,
                            const float* __restrict__ mlp_ws,
                            const float* __restrict__ w_out,
                            __half* __restrict__ feat,
                            __half* __restrict__ gw) {
    if (blockIdx.x >= FEAT_BLOCKS) {
        int i = (blockIdx.x - FEAT_BLOCKS) * blockDim.x + threadIdx.x;  // float4 idx
        const int WW4 = (HIDDEN * HIDDEN) / 4;                          // 65536
        const float* src;
        if (i < WW4)            src = w_in   + 4 * (size_t)i;
        else if (i < 4 * WW4)   src = mlp_ws + 4 * ((size_t)i - WW4);
        else                    src = w_out  + 4 * ((size_t)i - 4 * WW4);
        float4 v = *reinterpret_cast<const float4*>(src);
        reinterpret_cast<__half2*>(gw)[2 * i]     = __floats2half2_rn(v.x, v.y);
        reinterpret_cast<__half2*>(gw)[2 * i + 1] = __floats2half2_rn(v.z, v.w);
        return;
    }
    int w    = (blockIdx.x * blockDim.x + threadIdx.x) >> 5;
    int lane = threadIdx.x & 31;
    int s = w & (SEQ - 1);
    int c = chars[w];

    {
        const float4* bsrc = reinterpret_cast<const float4*>(byte_embed + (size_t)c * 256) + lane * 2;
        float4 v0 = bsrc[0];
        float4 v1 = bsrc[1];
        __half2 o[4];
        o[0] = __floats2half2_rn(v0.x, v0.y);
        o[1] = __floats2half2_rn(v0.z, v0.w);
        o[2] = __floats2half2_rn(v1.x, v1.y);
        o[3] = __floats2half2_rn(v1.z, v1.w);
        reinterpret_cast<uint4*>(feat + (size_t)w * HIDDEN)[lane] = *reinterpret_cast<uint4*>(o);
    }
    {
        int tl = c_plen[lane];
        long long h = 0;
        #pragma unroll
        for (int k = 0; k < 3; k++) {
            if (k < tl) {
                int off = c_poff[lane][k];
                long long tok = (s >= off) ? (long long)chars[w - off] : 0LL;
                h ^= (long long)((unsigned long long)tok *
                                 (unsigned long long)c_primes[(lane * 3 + k) % 24]);
            }
        }
        int idx_lo = (int)(h & (long long)(BUCKETS - 1));
        long long sp = c_primes[(lane * 3 + tl) % 24];
        long long prod = (long long)((unsigned long long)h * (unsigned long long)sp);
        long long h2 = h ^ (prod >> 16);
        int idx_hi = (int)(h2 & (long long)(BUCKETS - 1));
        float frac = ((float)(int)((h >> 3) & 255LL) / 255.0f) * 0.4f;
        float a = 1.0f - frac;

        const float* tab = hash_tables + (size_t)lane * BUCKETS * 8;
        const float4* lo = reinterpret_cast<const float4*>(tab + (size_t)idx_lo * 8);
        const float4* hi = reinterpret_cast<const float4*>(tab + (size_t)idx_hi * 8);
        float4 l0 = lo[0], l1 = lo[1];
        float4 h0 = hi[0], h1 = hi[1];
        __half2 o[4];
        o[0] = __floats2half2_rn(l0.x * a + h0.x * frac, l0.y * a + h0.y * frac);
        o[1] = __floats2half2_rn(l0.z * a + h0.z * frac, l0.w * a + h0.w * frac);
        o[2] = __floats2half2_rn(l1.x * a + h1.x * frac, l1.y * a + h1.y * frac);
        o[3] = __floats2half2_rn(l1.z * a + h1.z * frac, l1.w * a + h1.w * frac);
        reinterpret_cast<uint4*>(feat + (size_t)w * HIDDEN + 256)[lane] = *reinterpret_cast<uint4*>(o);
    }
}

// ---------------- HMMA GEMM: C = act(A @ W^T + bias) [+ Res] ----------------
// Block tile 128x128, 256 threads (8 warps, 2x4), warp tile 64x32.
// 3-stage padded smem ring, wait_group 1, ONE __syncthreads per iteration.
// Register diet (__launch_bounds__(256,3) -> <=85 regs): B frags loaded once
// per k16 (8 regs), A frags ping-pong 2-deep (8 regs) with one-ahead prefetch.
// Goal: 3 CTAs/SM (occ 24% -> ~36%) to hide LDSM->MMA latency and barriers.
template<bool RELU, bool HASRES, typename OT>
__global__ __launch_bounds__(256, 3) void gemm_kernel(
    const __half* __restrict__ A, const __half* __restrict__ W,
    const float* __restrict__ bias, const __half* __restrict__ Res,
    OT* __restrict__ C, int N) {

    extern __shared__ __align__(16) __half sh[];
    // layout: As[NSTAGE][BM][SPAD] then Bs[NSTAGE][BN][SPAD]
    __half* As0 = sh;
    __half* Bs0 = sh + NSTAGE * BM * SPAD;

    const int tid  = threadIdx.x;
    const int wid  = tid >> 5;
    const int lane = tid & 31;
    const int wm   = wid & 1;        // 0..1  (64 rows each)
    const int wn   = wid >> 1;       // 0..3  (32 cols each)
    const int m0   = blockIdx.x * BM;
    const int n0   = blockIdx.y * BN;

    float acc[4][4][4];
    #pragma unroll
    for (int i = 0; i < 4; i++)
        #pragma unroll
        for (int j = 0; j < 4; j++)
            #pragma unroll
            for (int k = 0; k < 4; k++) acc[i][j][k] = 0.0f;

    // per operand: 128 rows x 4 16B-chunks = 512 chunks; 256 threads -> 2 each
    auto load_stage = [&](int stage, int k0) {
        __half* Adst = As0 + stage * BM * SPAD;
        __half* Bdst = Bs0 + stage * BN * SPAD;
        #pragma unroll
        for (int it = 0; it < 2; it++) {
            int chunk = tid + it * 256;          // 0..511
            int r  = chunk >> 2;                 // row 0..127
            int cc = (chunk & 3) << 3;           // col 0,8,16,24
            const __half* ga = A + (size_t)(m0 + r) * KDIM + k0 + cc;
            uint32_t sa = (uint32_t)__cvta_generic_to_shared(Adst + r * SPAD + cc);
            asm volatile("cp.async.cg.shared.global [%0], [%1], 16;" :: "r"(sa), "l"(ga));
            const __half* gb = W + (size_t)(n0 + r) * KDIM + k0 + cc;
            uint32_t sb = (uint32_t)__cvta_generic_to_shared(Bdst + r * SPAD + cc);
            asm volatile("cp.async.cg.shared.global [%0], [%1], 16;" :: "r"(sb), "l"(gb));
        }
        asm volatile("cp.async.commit_group;" ::: "memory");
    };

    load_stage(0, 0);
    load_stage(1, BK);

    // per-thread invariant fragment offsets (halves)
    const int a_row_off = wm * 64 + (lane & 15);
    const int a_col_off = (lane >> 4) << 3;
    const int b_row_off = wn * 32 + (((lane >> 3) >> 1) << 3) + (lane & 7);
    const int b_col_off = ((lane >> 3) & 1) << 3;

    #pragma unroll 1
    for (int kt = 0; kt < NKIT; kt++) {
        if (kt == NKIT - 1)
            asm volatile("cp.async.wait_group 0;" ::: "memory");
        else
            asm volatile("cp.async.wait_group 1;" ::: "memory");
        __syncthreads();   // also protects slot (kt+2)%3 (last read at kt-1)

        if (kt + 2 < NKIT) load_stage((kt + 2) % NSTAGE, (kt + 2) * BK);

        const int st = kt % NSTAGE;
        const __half* Asrc = As0 + st * BM * SPAD;
        const __half* Bsrc = Bs0 + st * BN * SPAD;

        #pragma unroll
        for (int kk = 0; kk < 2; kk++) {       // two k16 steps per BK=32
            uint32_t af[2][4];                 // ping-pong A fragments
            uint32_t bf[4][2];

            // A fragment for mt=0 first (latency hidden behind B loads)
            {
                const __half* p = Asrc + a_row_off * SPAD + kk * 16 + a_col_off;
                uint32_t ad = (uint32_t)__cvta_generic_to_shared(p);
                asm volatile("ldmatrix.sync.aligned.m8n8.x4.shared.b16 {%0,%1,%2,%3}, [%4];\n"
                             : "=r"(af[0][0]), "=r"(af[0][1]), "=r"(af[0][2]), "=r"(af[0][3])
                             : "r"(ad));
            }
            // B fragments for all 4 n-tiles (reused by every mt)
            #pragma unroll
            for (int np = 0; np < 2; np++) {
                const __half* p = Bsrc + (b_row_off + np * 16) * SPAD + kk * 16 + b_col_off;
                uint32_t ad = (uint32_t)__cvta_generic_to_shared(p);
                asm volatile("ldmatrix.sync.aligned.m8n8.x4.shared.b16 {%0,%1,%2,%3}, [%4];\n"
                             : "=r"(bf[np * 2][0]), "=r"(bf[np * 2][1]),
                               "=r"(bf[np * 2 + 1][0]), "=r"(bf[np * 2 + 1][1])
                             : "r"(ad));
            }
            #pragma unroll
            for (int mt = 0; mt < 4; mt++) {
                if (mt < 3) {   // prefetch next A fragment while this mt computes
                    const __half* p = Asrc + (a_row_off + (mt + 1) * 16) * SPAD
                                           + kk * 16 + a_col_off;
                    uint32_t ad = (uint32_t)__cvta_generic_to_shared(p);
                    asm volatile("ldmatrix.sync.aligned.m8n8.x4.shared.b16 {%0,%1,%2,%3}, [%4];\n"
                                 : "=r"(af[(mt + 1) & 1][0]), "=r"(af[(mt + 1) & 1][1]),
                                   "=r"(af[(mt + 1) & 1][2]), "=r"(af[(mt + 1) & 1][3])
                                 : "r"(ad));
                }
                #pragma unroll
                for (int nt = 0; nt < 4; nt++)
                    asm volatile(
                        "mma.sync.aligned.m16n8k16.row.col.f32.f16.f16.f32 "
                        "{%0,%1,%2,%3}, {%4,%5,%6,%7}, {%8,%9}, {%0,%1,%2,%3};\n"
                        : "+f"(acc[mt][nt][0]), "+f"(acc[mt][nt][1]),
                          "+f"(acc[mt][nt][2]), "+f"(acc[mt][nt][3])
                        : "r"(af[mt & 1][0]), "r"(af[mt & 1][1]),
                          "r"(af[mt & 1][2]), "r"(af[mt & 1][3]),
                          "r"(bf[nt][0]), "r"(bf[nt][1]));
            }
        }
    }

    // ---- epilogue: bias (+relu) (+residual) ----
    #pragma unroll
    for (int nt = 0; nt < 4; nt++) {
        int col = n0 + wn * 32 + nt * 8 + ((lane & 3) << 1);
        float b0 = bias[col], b1 = bias[col + 1];
        #pragma unroll
        for (int mt = 0; mt < 4; mt++) {
            int row = m0 + wm * 64 + mt * 16 + (lane >> 2);
            #pragma unroll
            for (int half_ = 0; half_ < 2; half_++) {
                int r = row + half_ * 8;
                float v0 = acc[mt][nt][half_ * 2 + 0] + b0;
                float v1 = acc[mt][nt][half_ * 2 + 1] + b1;
                if (RELU) { v0 = fmaxf(v0, 0.0f); v1 = fmaxf(v1, 0.0f); }
                if (HASRES) {
                    __half2 rr = *reinterpret_cast<const __half2*>(&Res[(size_t)r * N + col]);
                    float2 rf = __half22float2(rr);
                    v0 += rf.x; v1 += rf.y;
                }
                if (sizeof(OT) == 2) {
                    *reinterpret_cast<__half2*>((__half*)C + (size_t)r * N + col) =
                        __floats2half2_rn(v0, v1);
                } else {
                    *reinterpret_cast<float2*>((float*)C + (size_t)r * N + col) =
                        make_float2(v0, v1);
                }
            }
        }
    }
}

// ---------------- launch ----------------
extern "C" void kernel_launch(void* const* d_in, const int* in_sizes, int n_in,
                              void* d_out, int out_size) {
    const int* chars           = (const int*)d_in[0];
    const float* byte_embed    = (const float*)d_in[1];
    const float* hash_tables   = (const float*)d_in[2];
    const float* w_in          = (const float*)d_in[3];
    const float* b_in          = (const float*)d_in[4];
    const float* mlp_ws        = (const float*)d_in[5];
    const float* mlp_bs        = (const float*)d_in[6];
    const float* w_out         = (const float*)d_in[7];
    const float* b_out         = (const float*)d_in[8];
    float* out                 = (float*)d_out;

    void *pf, *pa, *pb, *pw;
    cudaGetSymbolAddress(&pf, g_feat);
    cudaGetSymbolAddress(&pa, g_hA);
    cudaGetSymbolAddress(&pb, g_hB);
    cudaGetSymbolAddress(&pw, g_w);
    __half* feat = (__half*)pf;
    __half* hA   = (__half*)pa;
    __half* hB   = (__half*)pb;
    __half* gw   = (__half*)pw;

    const int SMEM = NSTAGE * (BM + BN) * SPAD * 2;   // 61440 B
    cudaFuncSetAttribute(gemm_kernel<true,  false, __half>, cudaFuncAttributeMaxDynamicSharedMemorySize, SMEM);
    cudaFuncSetAttribute(gemm_kernel<true,  true,  __half>, cudaFuncAttributeMaxDynamicSharedMemorySize, SMEM);
    cudaFuncSetAttribute(gemm_kernel<false, false, float >, cudaFuncAttributeMaxDynamicSharedMemorySize, SMEM);

    // fused features + weight convert (single launch)
    prep_kernel<<<FEAT_BLOCKS + WCVT_BLOCKS, 256>>>(
        chars, byte_embed, hash_tables, w_in, mlp_ws, w_out, feat, gw);

    dim3 blk(256);
    dim3 g512(M_TOK / BM, HIDDEN / BN);   // (512, 4)
    dim3 g1024(M_TOK / BM, VOCAB / BN);   // (512, 8)
    const int WW = HIDDEN * HIDDEN;

    // h = relu(feat @ w_in^T + b_in)
    gemm_kernel<true, false, __half><<<g512, blk, SMEM>>>(feat, gw, b_in, nullptr, hA, HIDDEN);
    // residual blocks: h = relu(h @ W^T + b) + h
    gemm_kernel<true, true, __half><<<g512, blk, SMEM>>>(hA, gw + 1 * WW, mlp_bs + 0 * HIDDEN, hA, hB, HIDDEN);
    gemm_kernel<true, true, __half><<<g512, blk, SMEM>>>(hB, gw + 2 * WW, mlp_bs + 1 * HIDDEN, hB, hA, HIDDEN);
    gemm_kernel<true, true, __half><<<g512, blk, SMEM>>>(hA, gw + 3 * WW, mlp_bs + 2 * HIDDEN, hA, hB, HIDDEN);
    // logits = h @ w_out^T + b_out  (fp32 out)
    gemm_kernel<false, false, float><<<g1024, blk, SMEM>>>(hB, gw + 4 * WW, b_out, nullptr, out, VOCAB);
}

// round 15
// speedup vs baseline: 1.3842x; 1.3842x over previous
#include <cuda_runtime.h>
#include <cuda_fp16.h>
#include <stdint.h>

// ---------------- problem constants ----------------
#define SEQ      2048
#define M_TOK    65536          // 32 * 2048 tokens
#define HIDDEN   512
#define VOCAB    1024
#define KDIM     512
#define BUCKETS  4096

// ---------------- GEMM tiling ----------------
#define BM 128                  // block M tile
#define BN 128                  // block N tile
#define BK 64                   // K chunk (halves) -- doubled to halve sync count
#define NKIT (KDIM / BK)        // 8
#define NSTAGE 2
#define SPAD 72                 // padded smem row stride in halves (conflict-free ldmatrix)

// ---------------- scratch (no allocs allowed) ----------------
__device__ __half g_feat[(size_t)M_TOK * HIDDEN];   // 64 MB
__device__ __half g_hA  [(size_t)M_TOK * HIDDEN];   // 64 MB
__device__ __half g_hB  [(size_t)M_TOK * HIDDEN];   // 64 MB
__device__ __half g_w   [4 * HIDDEN * HIDDEN + VOCAB * HIDDEN]; // fp16 weights

// ---------------- hash constants (bit-exact vs reference) ----------------
__constant__ long long c_primes[24] = {
    2654435761LL, 2246822519LL, 3266489917LL, 2028178513LL, 1220703125LL,
    1610612741LL, 805306457LL,  402653189LL,  3674653429LL, 2860486313LL,
    1073676287LL, 2971215073LL, 1500450271LL, 3267000013LL, 2654435789LL,
    4049292737LL, 2246822531LL, 3266489927LL, 2028178519LL, 1220703133LL,
    1610612743LL, 805306459LL,  402653191LL,  3674653433LL};

__constant__ int c_plen[32] = {1,1,1,1,1,1,1,1,
                               2,2,2,2,2,2,2,2,2,2,2,2,
                               3,3,3,3,3,3,3,3,
                               2,2,2,2};
__constant__ int c_poff[32][3] = {
    {1,0,0},{2,0,0},{3,0,0},{4,0,0},{5,0,0},{6,0,0},{7,0,0},{8,0,0},
    {1,2,0},{2,3,0},{3,4,0},{1,3,0},{2,4,0},{1,4,0},{1,5,0},{2,5,0},
    {3,5,0},{1,6,0},{2,6,0},{1,7,0},
    {1,2,3},{1,2,4},{1,3,5},{2,3,4},{1,2,5},{1,3,4},{2,4,6},{1,4,7},
    {1,8,0},{1,9,0},{1,10,0},{1,11,0}};

// ---------------- fused feature + weight-convert kernel ----------------
#define FEAT_BLOCKS 8192
#define WCVT_F4     393216      // (4*512*512 + 1024*512) / 4 float4 elements
#define WCVT_BLOCKS 1536        // WCVT_F4 / 256

__global__ void prep_kernel(const int* __restrict__ chars,
                            const float* __restrict__ byte_embed,
                            const float* __restrict__ hash_tables,
                            const float* __restrict__ w_in,
                            const float* __restrict__ mlp_ws,
                            const float* __restrict__ w_out,
                            __half* __restrict__ feat,
                            __half* __restrict__ gw) {
    if (blockIdx.x >= FEAT_BLOCKS) {
        int i = (blockIdx.x - FEAT_BLOCKS) * blockDim.x + threadIdx.x;  // float4 idx
        const int WW4 = (HIDDEN * HIDDEN) / 4;                          // 65536
        const float* src;
        if (i < WW4)            src = w_in   + 4 * (size_t)i;
        else if (i < 4 * WW4)   src = mlp_ws + 4 * ((size_t)i - WW4);
        else                    src = w_out  + 4 * ((size_t)i - 4 * WW4);
        float4 v = *reinterpret_cast<const float4*>(src);
        reinterpret_cast<__half2*>(gw)[2 * i]     = __floats2half2_rn(v.x, v.y);
        reinterpret_cast<__half2*>(gw)[2 * i + 1] = __floats2half2_rn(v.z, v.w);
        return;
    }
    int w    = (blockIdx.x * blockDim.x + threadIdx.x) >> 5;
    int lane = threadIdx.x & 31;
    int s = w & (SEQ - 1);
    int c = chars[w];

    {
        const float4* bsrc = reinterpret_cast<const float4*>(byte_embed + (size_t)c * 256) + lane * 2;
        float4 v0 = bsrc[0];
        float4 v1 = bsrc[1];
        __half2 o[4];
        o[0] = __floats2half2_rn(v0.x, v0.y);
        o[1] = __floats2half2_rn(v0.z, v0.w);
        o[2] = __floats2half2_rn(v1.x, v1.y);
        o[3] = __floats2half2_rn(v1.z, v1.w);
        reinterpret_cast<uint4*>(feat + (size_t)w * HIDDEN)[lane] = *reinterpret_cast<uint4*>(o);
    }
    {
        int tl = c_plen[lane];
        long long h = 0;
        #pragma unroll
        for (int k = 0; k < 3; k++) {
            if (k < tl) {
                int off = c_poff[lane][k];
                long long tok = (s >= off) ? (long long)chars[w - off] : 0LL;
                h ^= (long long)((unsigned long long)tok *
                                 (unsigned long long)c_primes[(lane * 3 + k) % 24]);
            }
        }
        int idx_lo = (int)(h & (long long)(BUCKETS - 1));
        long long sp = c_primes[(lane * 3 + tl) % 24];
        long long prod = (long long)((unsigned long long)h * (unsigned long long)sp);
        long long h2 = h ^ (prod >> 16);
        int idx_hi = (int)(h2 & (long long)(BUCKETS - 1));
        float frac = ((float)(int)((h >> 3) & 255LL) / 255.0f) * 0.4f;
        float a = 1.0f - frac;

        const float* tab = hash_tables + (size_t)lane * BUCKETS * 8;
        const float4* lo = reinterpret_cast<const float4*>(tab + (size_t)idx_lo * 8);
        const float4* hi = reinterpret_cast<const float4*>(tab + (size_t)idx_hi * 8);
        float4 l0 = lo[0], l1 = lo[1];
        float4 h0 = hi[0], h1 = hi[1];
        __half2 o[4];
        o[0] = __floats2half2_rn(l0.x * a + h0.x * frac, l0.y * a + h0.y * frac);
        o[1] = __floats2half2_rn(l0.z * a + h0.z * frac, l0.w * a + h0.w * frac);
        o[2] = __floats2half2_rn(l1.x * a + h1.x * frac, l1.y * a + h1.y * frac);
        o[3] = __floats2half2_rn(l1.z * a + h1.z * frac, l1.w * a + h1.w * frac);
        reinterpret_cast<uint4*>(feat + (size_t)w * HIDDEN + 256)[lane] = *reinterpret_cast<uint4*>(o);
    }
}

// ---------------- HMMA GEMM: C = act(A @ W^T + bias) [+ Res] ----------------
// Block tile 128x128, 256 threads (8 warps, 2x4), warp tile 64x32 (proven R13
// fragment mapping: ALL A fragments loaded up front each k16). BK=64 with a
// 2-stage ring: HALF the wait_group/__syncthreads events of R13, 4 k16 steps
// of uninterrupted MMA issue per chunk. smem 73.7KB -> 2 CTAs/SM.
template<bool RELU, bool HASRES, typename OT>
__global__ __launch_bounds__(256) void gemm_kernel(
    const __half* __restrict__ A, const __half* __restrict__ W,
    const float* __restrict__ bias, const __half* __restrict__ Res,
    OT* __restrict__ C, int N) {

    extern __shared__ __align__(16) __half sh[];
    // layout: As[NSTAGE][BM][SPAD] then Bs[NSTAGE][BN][SPAD]
    __half* As0 = sh;
    __half* Bs0 = sh + NSTAGE * BM * SPAD;

    const int tid  = threadIdx.x;
    const int wid  = tid >> 5;
    const int lane = tid & 31;
    const int wm   = wid & 1;        // 0..1  (64 rows each)
    const int wn   = wid >> 1;       // 0..3  (32 cols each)
    const int m0   = blockIdx.x * BM;
    const int n0   = blockIdx.y * BN;

    float acc[4][4][4];
    #pragma unroll
    for (int i = 0; i < 4; i++)
        #pragma unroll
        for (int j = 0; j < 4; j++)
            #pragma unroll
            for (int k = 0; k < 4; k++) acc[i][j][k] = 0.0f;

    // per operand: 128 rows x 8 16B-chunks = 1024 chunks; 256 threads -> 4 each
    auto load_stage = [&](int stage, int k0) {
        __half* Adst = As0 + stage * BM * SPAD;
        __half* Bdst = Bs0 + stage * BN * SPAD;
        #pragma unroll
        for (int it = 0; it < 4; it++) {
            int chunk = tid + it * 256;          // 0..1023
            int r  = chunk >> 3;                 // row 0..127
            int cc = (chunk & 7) << 3;           // col 0,8,...,56
            const __half* ga = A + (size_t)(m0 + r) * KDIM + k0 + cc;
            uint32_t sa = (uint32_t)__cvta_generic_to_shared(Adst + r * SPAD + cc);
            asm volatile("cp.async.cg.shared.global [%0], [%1], 16;" :: "r"(sa), "l"(ga));
            const __half* gb = W + (size_t)(n0 + r) * KDIM + k0 + cc;
            uint32_t sb = (uint32_t)__cvta_generic_to_shared(Bdst + r * SPAD + cc);
            asm volatile("cp.async.cg.shared.global [%0], [%1], 16;" :: "r"(sb), "l"(gb));
        }
        asm volatile("cp.async.commit_group;" ::: "memory");
    };

    load_stage(0, 0);

    #pragma unroll 1
    for (int kt = 0; kt < NKIT; kt++) {
        asm volatile("cp.async.wait_group 0;" ::: "memory");
        __syncthreads();
        // prefetch next chunk into the other stage; overlaps this chunk's MMAs
        if (kt + 1 < NKIT) load_stage((kt + 1) & 1, (kt + 1) * BK);

        const int st = kt & 1;
        const __half* Asrc = As0 + st * BM * SPAD;
        const __half* Bsrc = Bs0 + st * BN * SPAD;

        #pragma unroll
        for (int kk = 0; kk < 4; kk++) {       // four k16 steps per BK=64
            uint32_t af[4][4];
            uint32_t bf[4][2];
            #pragma unroll
            for (int mt = 0; mt < 4; mt++) {
                const __half* p = Asrc + (wm * 64 + mt * 16 + (lane & 15)) * SPAD
                                       + kk * 16 + ((lane >> 4) << 3);
                uint32_t ad = (uint32_t)__cvta_generic_to_shared(p);
                asm volatile("ldmatrix.sync.aligned.m8n8.x4.shared.b16 {%0,%1,%2,%3}, [%4];\n"
                             : "=r"(af[mt][0]), "=r"(af[mt][1]), "=r"(af[mt][2]), "=r"(af[mt][3])
                             : "r"(ad));
            }
            #pragma unroll
            for (int np = 0; np < 2; np++) {
                int blk = lane >> 3, r = lane & 7;
                const __half* p = Bsrc + (wn * 32 + np * 16 + ((blk >> 1) << 3) + r) * SPAD
                                       + kk * 16 + ((blk & 1) << 3);
                uint32_t ad = (uint32_t)__cvta_generic_to_shared(p);
                asm volatile("ldmatrix.sync.aligned.m8n8.x4.shared.b16 {%0,%1,%2,%3}, [%4];\n"
                             : "=r"(bf[np * 2][0]), "=r"(bf[np * 2][1]),
                               "=r"(bf[np * 2 + 1][0]), "=r"(bf[np * 2 + 1][1])
                             : "r"(ad));
            }
            #pragma unroll
            for (int mt = 0; mt < 4; mt++)
                #pragma unroll
                for (int nt = 0; nt < 4; nt++)
                    asm volatile(
                        "mma.sync.aligned.m16n8k16.row.col.f32.f16.f16.f32 "
                        "{%0,%1,%2,%3}, {%4,%5,%6,%7}, {%8,%9}, {%0,%1,%2,%3};\n"
                        : "+f"(acc[mt][nt][0]), "+f"(acc[mt][nt][1]),
                          "+f"(acc[mt][nt][2]), "+f"(acc[mt][nt][3])
                        : "r"(af[mt][0]), "r"(af[mt][1]), "r"(af[mt][2]), "r"(af[mt][3]),
                          "r"(bf[nt][0]), "r"(bf[nt][1]));
        }
    }

    // ---- epilogue: bias (+relu) (+residual) ----
    #pragma unroll
    for (int nt = 0; nt < 4; nt++) {
        int col = n0 + wn * 32 + nt * 8 + ((lane & 3) << 1);
        float b0 = bias[col], b1 = bias[col + 1];
        #pragma unroll
        for (int mt = 0; mt < 4; mt++) {
            int row = m0 + wm * 64 + mt * 16 + (lane >> 2);
            #pragma unroll
            for (int half_ = 0; half_ < 2; half_++) {
                int r = row + half_ * 8;
                float v0 = acc[mt][nt][half_ * 2 + 0] + b0;
                float v1 = acc[mt][nt][half_ * 2 + 1] + b1;
                if (RELU) { v0 = fmaxf(v0, 0.0f); v1 = fmaxf(v1, 0.0f); }
                if (HASRES) {
                    __half2 rr = *reinterpret_cast<const __half2*>(&Res[(size_t)r * N + col]);
                    float2 rf = __half22float2(rr);
                    v0 += rf.x; v1 += rf.y;
                }
                if (sizeof(OT) == 2) {
                    *reinterpret_cast<__half2*>((__half*)C + (size_t)r * N + col) =
                        __floats2half2_rn(v0, v1);
                } else {
                    *reinterpret_cast<float2*>((float*)C + (size_t)r * N + col) =
                        make_float2(v0, v1);
                }
            }
        }
    }
}

// ---------------- launch ----------------
extern "C" void kernel_launch(void* const* d_in, const int* in_sizes, int n_in,
                              void* d_out, int out_size) {
    const int* chars           = (const int*)d_in[0];
    const float* byte_embed    = (const float*)d_in[1];
    const float* hash_tables   = (const float*)d_in[2];
    const float* w_in          = (const float*)d_in[3];
    const float* b_in          = (const float*)d_in[4];
    const float* mlp_ws        = (const float*)d_in[5];
    const float* mlp_bs        = (const float*)d_in[6];
    const float* w_out         = (const float*)d_in[7];
    const float* b_out         = (const float*)d_in[8];
    float* out                 = (float*)d_out;

    void *pf, *pa, *pb, *pw;
    cudaGetSymbolAddress(&pf, g_feat);
    cudaGetSymbolAddress(&pa, g_hA);
    cudaGetSymbolAddress(&pb, g_hB);
    cudaGetSymbolAddress(&pw, g_w);
    __half* feat = (__half*)pf;
    __half* hA   = (__half*)pa;
    __half* hB   = (__half*)pb;
    __half* gw   = (__half*)pw;

    const int SMEM = NSTAGE * (BM + BN) * SPAD * 2;   // 73728 B
    cudaFuncSetAttribute(gemm_kernel<true,  false, __half>, cudaFuncAttributeMaxDynamicSharedMemorySize, SMEM);
    cudaFuncSetAttribute(gemm_kernel<true,  true,  __half>, cudaFuncAttributeMaxDynamicSharedMemorySize, SMEM);
    cudaFuncSetAttribute(gemm_kernel<false, false, float >, cudaFuncAttributeMaxDynamicSharedMemorySize, SMEM);

    // fused features + weight convert (single launch)
    prep_kernel<<<FEAT_BLOCKS + WCVT_BLOCKS, 256>>>(
        chars, byte_embed, hash_tables, w_in, mlp_ws, w_out, feat, gw);

    dim3 blk(256);
    dim3 g512(M_TOK / BM, HIDDEN / BN);   // (512, 4)
    dim3 g1024(M_TOK / BM, VOCAB / BN);   // (512, 8)
    const int WW = HIDDEN * HIDDEN;

    // h = relu(feat @ w_in^T + b_in)
    gemm_kernel<true, false, __half><<<g512, blk, SMEM>>>(feat, gw, b_in, nullptr, hA, HIDDEN);
    // residual blocks: h = relu(h @ W^T + b) + h
    gemm_kernel<true, true, __half><<<g512, blk, SMEM>>>(hA, gw + 1 * WW, mlp_bs + 0 * HIDDEN, hA, hB, HIDDEN);
    gemm_kernel<true, true, __half><<<g512, blk, SMEM>>>(hB, gw + 2 * WW, mlp_bs + 1 * HIDDEN, hB, hA, HIDDEN);
    gemm_kernel<true, true, __half><<<g512, blk, SMEM>>>(hA, gw + 3 * WW, mlp_bs + 2 * HIDDEN, hA, hB, HIDDEN);
    // logits = h @ w_out^T + b_out  (fp32 out)
    gemm_kernel<false, false, float><<<g1024, blk, SMEM>>>(hB, gw + 4 * WW, b_out, nullptr, out, VOCAB);
}